// round 4
// baseline (speedup 1.0000x reference)
#include <cuda_runtime.h>
#include <cstdint>

#define NFEAT 784
#define NCLS  10
#define KC    16
#define NT    49                     // 784 / 16
#define TPB   256
#define ROWSPC 222                   // rows per CTA (296 CTAs cover 65536)
#define ROWS_AL 256                  // smem rows allocated (uniform indexing)
#define NCHUNK (ROWSPC * 4)          // 888 16B-chunks per tile
#define XSTR  20                     // 16 + 4 pad: conflict-free LDS.128
#define NBUF  3
#define XS_FLOATS (NBUF * ROWS_AL * XSTR)   // 15360
#define AS_FLOATS (NCLS * NFEAT)            // 7840
#define RED_FLOATS (8 * NCLS)               // 80
#define SMEM_FLOATS (XS_FLOATS + AS_FLOATS + RED_FLOATS + NCLS + 2)
#define SMEM_BYTES  (SMEM_FLOATS * 4)       // ~93 KB

// ---------------------------------------------------------------------------
__device__ __forceinline__ void cp_async16(uint32_t saddr, const void* gptr) {
    asm volatile("cp.async.cg.shared.global [%0], [%1], 16;\n"
                 :: "r"(saddr), "l"(gptr));
}
#define CP_COMMIT() asm volatile("cp.async.commit_group;\n" ::: "memory")
#define CP_WAIT(n)  asm volatile("cp.async.wait_group %0;\n" :: "n"(n) : "memory")
#define FMA_F32X2(d, a, b) \
    asm volatile("fma.rn.f32x2 %0, %1, %2, %0;" : "+l"(d) : "l"(a), "l"(b))

extern __shared__ float smem[];

// Stage tile t: x[row0 .. row0+221][t*16 .. t*16+15], coalesced, predicated.
__device__ __forceinline__ void issue_tile(const float* __restrict__ x,
                                           int row0, int Brows, int tid, int t) {
    const int k0 = t * KC;
    float* xb = smem + (t % NBUF) * ROWS_AL * XSTR;
#pragma unroll
    for (int i = 0; i < 4; ++i) {
        int g = tid + i * TPB;            // 0..1023, use 0..887
        if (g < NCHUNK) {
            int r  = g >> 2;
            int ch = g & 3;
            int row = row0 + r;
            if (row >= Brows) row = Brows - 1;   // clamp (reads discarded)
            const float* gp = x + (size_t)row * NFEAT + k0 + ch * 4;
            uint32_t sa = (uint32_t)__cvta_generic_to_shared(xb + r * XSTR + ch * 4);
            cp_async16(sa, gp);
        }
    }
    CP_COMMIT();
}

// ---------------------------------------------------------------------------
// Fused kernel: per-CTA fold of sparse+FC into A[10,784] (shared), then
// [222 rows] @ A^T + c0, softmax. 1 row/thread, 16 warps/SM (2 CTAs x 8),
// grid=2*SMs for perfect wave balance, 3-buffer cp.async pipeline.
// ---------------------------------------------------------------------------
__global__ void __launch_bounds__(TPB, 2)
fused_kernel(const float* __restrict__ x,
             const float* __restrict__ W,
             const float* __restrict__ Bsp,
             const float* __restrict__ fcw,
             const float* __restrict__ fcb,
             float* __restrict__ out, int Brows)
{
    float* As  = smem + XS_FLOATS;            // [10][784]
    float* red = As + AS_FLOATS;              // [8][10]
    float* c0s = red + RED_FLOATS;            // [10]

    const int tid  = threadIdx.x;
    const int row0 = blockIdx.x * ROWSPC;

    // Kick DRAM immediately: prefetch tiles 0 and 1 while we build A.
    issue_tile(x, row0, Brows, tid, 0);
    issue_tile(x, row0, Brows, tid, 1);

    // ---- build A and c0 in shared ----
    float part[NCLS];
#pragma unroll
    for (int c = 0; c < NCLS; ++c) part[c] = 0.f;

    for (int k = tid; k < NFEAT; k += TPB) {
        // scatter column map (faithful to the reference's i=782 wraparound bug)
        int c0i = (k == NFEAT - 2) ? 0 : k;
        int c1i = (k == NFEAT - 2) ? 1 : ((k + 1 == NFEAT) ? 0 : k + 1);
        float w0 = W[2*k],   w1 = W[2*k+1];
        float b0 = Bsp[2*k], b1 = Bsp[2*k+1];
#pragma unroll
        for (int c = 0; c < NCLS; ++c) {
            float f0 = __ldg(fcw + c * NFEAT + c0i);
            float f1 = __ldg(fcw + c * NFEAT + c1i);
            As[c * NFEAT + k] = f0 * w0 + f1 * w1;
            part[c] += f0 * b0 + f1 * b1;
        }
    }
#pragma unroll
    for (int off = 16; off; off >>= 1)
#pragma unroll
        for (int c = 0; c < NCLS; ++c)
            part[c] += __shfl_down_sync(0xffffffffu, part[c], off);
    if ((tid & 31) == 0)
#pragma unroll
        for (int c = 0; c < NCLS; ++c) red[(tid >> 5) * NCLS + c] = part[c];
    __syncthreads();
    if (tid < NCLS) {
        float s = fcb[tid];
#pragma unroll
        for (int w = 0; w < 8; ++w) s += red[w * NCLS + tid];
        c0s[tid] = s;
    }
    // (A stores + c0s ordered before first use by the loop's first barrier)

    // ---- main GEMV loop: 1 row/thread ----
    unsigned long long acc[NCLS];
#pragma unroll
    for (int c = 0; c < NCLS; ++c) acc[c] = 0ULL;

    const float* Aptr = As;
    for (int t = 0; t < NT; ++t) {
        if (t == NT - 1) { CP_WAIT(0); } else { CP_WAIT(1); }
        __syncthreads();          // tile t visible; buf (t+2)%3 fully consumed
        if (t + 2 < NT) issue_tile(x, row0, Brows, tid, t + 2);

        const float* xr = smem + (t % NBUF) * ROWS_AL * XSTR + tid * XSTR;
#pragma unroll
        for (int kc = 0; kc < 4; ++kc) {
            ulonglong2 xv = *(const ulonglong2*)(xr + kc * 4);
#pragma unroll
            for (int c = 0; c < NCLS; ++c) {
                ulonglong2 av = *(const ulonglong2*)(Aptr + c * NFEAT + kc * 4);
                FMA_F32X2(acc[c], xv.x, av.x);
                FMA_F32X2(acc[c], xv.y, av.y);
            }
        }
        Aptr += KC;
    }

    // ---- epilogue: unpack pair-sums, + const, softmax, store ----
    float logit[NCLS];
#pragma unroll
    for (int c = 0; c < NCLS; ++c) {
        float lo = __uint_as_float((unsigned)(acc[c] & 0xffffffffu));
        float hi = __uint_as_float((unsigned)(acc[c] >> 32));
        logit[c] = lo + hi + c0s[c];
    }
    float m = logit[0];
#pragma unroll
    for (int c = 1; c < NCLS; ++c) m = fmaxf(m, logit[c]);
    float ssum = 0.f;
#pragma unroll
    for (int c = 0; c < NCLS; ++c) { logit[c] = __expf(logit[c] - m); ssum += logit[c]; }
    float inv = 1.0f / ssum;

    const int row = row0 + tid;
    if (tid < ROWSPC && row < Brows) {
        float2* po = (float2*)(out + (size_t)row * NCLS);
#pragma unroll
        for (int c = 0; c < NCLS; c += 2)
            po[c >> 1] = make_float2(logit[c] * inv, logit[c + 1] * inv);
    }
}

// ---------------------------------------------------------------------------
extern "C" void kernel_launch(void* const* d_in, const int* in_sizes, int n_in,
                              void* d_out, int out_size) {
    const float* x   = (const float*)d_in[0];
    const float* W   = (const float*)d_in[1];
    const float* bsp = (const float*)d_in[2];
    const float* fcw = (const float*)d_in[3];
    const float* fcb = (const float*)d_in[4];
    float* out = (float*)d_out;
    const int Brows = in_sizes[0] / NFEAT;

    cudaFuncSetAttribute(fused_kernel,
                         cudaFuncAttributeMaxDynamicSharedMemorySize, SMEM_BYTES);

    const int grid = (Brows + ROWSPC - 1) / ROWSPC;   // 296 for B=65536
    fused_kernel<<<grid, TPB, SMEM_BYTES>>>(x, W, bsp, fcw, fcb, out, Brows);
}

// round 5
// speedup vs baseline: 1.4032x; 1.4032x over previous
#include <cuda_runtime.h>
#include <cstdint>

#define NFEAT 784
#define NCLS  10
#define KC    16
#define NT    49                     // 784 / 16
#define TPB   224                    // 7 warps
#define NWARP 7
#define RPT   2
#define ROWSPW 64                    // rows per warp
#define ROWSPC (NWARP * ROWSPW)      // 448 rows per CTA -> grid 147
#define XSTR  20                     // 16 + 4 pad: conflict-free LDS.128
#define NBUF  4                      // warp-private ring depth
#define XS_FLOATS (NWARP * NBUF * ROWSPW * XSTR)   // 35840
#define AS_FLOATS (NCLS * NFEAT)                   // 7840
#define RED_FLOATS (NWARP * NCLS)                  // 70
#define SMEM_FLOATS (XS_FLOATS + AS_FLOATS + RED_FLOATS + 2)
#define SMEM_BYTES  (SMEM_FLOATS * 4)              // ~174.8 KB -> 1 CTA/SM

// ---------------------------------------------------------------------------
__device__ __forceinline__ void cp_async16(uint32_t saddr, const void* gptr) {
    asm volatile("cp.async.cg.shared.global [%0], [%1], 16;\n"
                 :: "r"(saddr), "l"(gptr));
}
#define CP_COMMIT() asm volatile("cp.async.commit_group;\n" ::: "memory")
#define CP_WAIT(n)  asm volatile("cp.async.wait_group %0;\n" :: "n"(n) : "memory")
#define FMA_F32X2(d, a, b) \
    asm volatile("fma.rn.f32x2 %0, %1, %2, %0;" : "+l"(d) : "l"(a), "l"(b))

extern __shared__ float smem[];

// Warp-private stage of tile t: this warp's 64 rows x 16 k, 8 chunks/lane,
// one cp.async group. No CTA-level synchronization needed, ever.
__device__ __forceinline__ void issue_tile(const float* __restrict__ x,
                                           float* xw, int wrow0, int Brows,
                                           int lane, int t) {
    const int k0 = t * KC;
    float* xb = xw + (t & (NBUF - 1)) * ROWSPW * XSTR;
#pragma unroll
    for (int i = 0; i < 8; ++i) {
        int g  = lane + i * 32;        // 0..255: (row, 16B-chunk)
        int r  = g >> 2;
        int ch = g & 3;
        int row = wrow0 + r;
        if (row >= Brows) row = Brows - 1;   // clamp (reads discarded)
        const float* gp = x + (size_t)row * NFEAT + k0 + ch * 4;
        uint32_t sa = (uint32_t)__cvta_generic_to_shared(xb + r * XSTR + ch * 4);
        cp_async16(sa, gp);
    }
    CP_COMMIT();
}

// ---------------------------------------------------------------------------
// Fused, barrier-free mainloop: per-CTA fold of sparse+FC into A[10,784]
// (shared, read-only broadcast), then each warp independently streams its own
// 64 rows through a private 4-deep cp.async ring. 2 rows/thread, f32x2 FMA.
// ---------------------------------------------------------------------------
__global__ void __launch_bounds__(TPB, 1)
fused_kernel(const float* __restrict__ x,
             const float* __restrict__ W,
             const float* __restrict__ Bsp,
             const float* __restrict__ fcw,
             const float* __restrict__ fcb,
             float* __restrict__ out, int Brows)
{
    float* As  = smem + XS_FLOATS;            // [10][784]
    float* red = As + AS_FLOATS;              // [7][10]

    const int tid  = threadIdx.x;
    const int wid  = tid >> 5;
    const int lane = tid & 31;
    const int wrow0 = blockIdx.x * ROWSPC + wid * ROWSPW;
    float* xw = smem + wid * (NBUF * ROWSPW * XSTR);

    // Kick DRAM immediately: 3 tiles in flight per warp while A is built.
    issue_tile(x, xw, wrow0, Brows, lane, 0);
    issue_tile(x, xw, wrow0, Brows, lane, 1);
    issue_tile(x, xw, wrow0, Brows, lane, 2);

    // ---- build A and per-warp bias partials in shared ----
    float part[NCLS];
#pragma unroll
    for (int c = 0; c < NCLS; ++c) part[c] = 0.f;

    for (int k = tid; k < NFEAT; k += TPB) {
        // scatter column map (faithful to the reference's i=782 wraparound bug)
        int c0i = (k == NFEAT - 2) ? 0 : k;
        int c1i = (k == NFEAT - 2) ? 1 : ((k + 1 == NFEAT) ? 0 : k + 1);
        float w0 = W[2*k],   w1 = W[2*k+1];
        float b0 = Bsp[2*k], b1 = Bsp[2*k+1];
#pragma unroll
        for (int c = 0; c < NCLS; ++c) {
            float f0 = __ldg(fcw + c * NFEAT + c0i);
            float f1 = __ldg(fcw + c * NFEAT + c1i);
            As[c * NFEAT + k] = f0 * w0 + f1 * w1;
            part[c] += f0 * b0 + f1 * b1;
        }
    }
#pragma unroll
    for (int off = 16; off; off >>= 1)
#pragma unroll
        for (int c = 0; c < NCLS; ++c)
            part[c] += __shfl_down_sync(0xffffffffu, part[c], off);
    if (lane == 0)
#pragma unroll
        for (int c = 0; c < NCLS; ++c) red[wid * NCLS + c] = part[c];
    __syncthreads();     // the ONLY barrier: A + red visible to all warps

    // ---- barrier-free main GEMV loop: 2 rows/thread ----
    unsigned long long acc0[NCLS], acc1[NCLS];
#pragma unroll
    for (int c = 0; c < NCLS; ++c) { acc0[c] = 0ULL; acc1[c] = 0ULL; }

    const float* Aptr = As;
    for (int t = 0; t < NT; ++t) {
        if (t < NT - 2)      { CP_WAIT(2); }
        else if (t == NT - 2){ CP_WAIT(1); }
        else                 { CP_WAIT(0); }

        const float* xb  = xw + (t & (NBUF - 1)) * ROWSPW * XSTR;
        const float* xr0 = xb + lane * XSTR;
        const float* xr1 = xb + (32 + lane) * XSTR;
#pragma unroll
        for (int kc = 0; kc < 4; ++kc) {
            ulonglong2 v0 = *(const ulonglong2*)(xr0 + kc * 4);
            ulonglong2 v1 = *(const ulonglong2*)(xr1 + kc * 4);
#pragma unroll
            for (int c = 0; c < NCLS; ++c) {
                ulonglong2 av = *(const ulonglong2*)(Aptr + c * NFEAT + kc * 4);
                FMA_F32X2(acc0[c], v0.x, av.x);
                FMA_F32X2(acc0[c], v0.y, av.y);
                FMA_F32X2(acc1[c], v1.x, av.x);
                FMA_F32X2(acc1[c], v1.y, av.y);
            }
        }
        Aptr += KC;
        if (t + 3 < NT) issue_tile(x, xw, wrow0, Brows, lane, t + 3);
    }

    // ---- epilogue: bias from red (broadcast reads), softmax, store ----
    float c0v[NCLS];
#pragma unroll
    for (int c = 0; c < NCLS; ++c) {
        float s = __ldg(fcb + c);
#pragma unroll
        for (int w = 0; w < NWARP; ++w) s += red[w * NCLS + c];
        c0v[c] = s;
    }

#pragma unroll
    for (int rsel = 0; rsel < RPT; ++rsel) {
        const unsigned long long* acc = rsel ? acc1 : acc0;
        float logit[NCLS];
#pragma unroll
        for (int c = 0; c < NCLS; ++c) {
            float lo = __uint_as_float((unsigned)(acc[c] & 0xffffffffu));
            float hi = __uint_as_float((unsigned)(acc[c] >> 32));
            logit[c] = lo + hi + c0v[c];
        }
        float m = logit[0];
#pragma unroll
        for (int c = 1; c < NCLS; ++c) m = fmaxf(m, logit[c]);
        float ssum = 0.f;
#pragma unroll
        for (int c = 0; c < NCLS; ++c) { logit[c] = __expf(logit[c] - m); ssum += logit[c]; }
        float inv = 1.0f / ssum;

        const int row = wrow0 + lane + rsel * 32;
        if (row < Brows) {
            float2* po = (float2*)(out + (size_t)row * NCLS);
#pragma unroll
            for (int c = 0; c < NCLS; c += 2)
                po[c >> 1] = make_float2(logit[c] * inv, logit[c + 1] * inv);
        }
    }
}

// ---------------------------------------------------------------------------
extern "C" void kernel_launch(void* const* d_in, const int* in_sizes, int n_in,
                              void* d_out, int out_size) {
    const float* x   = (const float*)d_in[0];
    const float* W   = (const float*)d_in[1];
    const float* bsp = (const float*)d_in[2];
    const float* fcw = (const float*)d_in[3];
    const float* fcb = (const float*)d_in[4];
    float* out = (float*)d_out;
    const int Brows = in_sizes[0] / NFEAT;

    cudaFuncSetAttribute(fused_kernel,
                         cudaFuncAttributeMaxDynamicSharedMemorySize, SMEM_BYTES);

    const int grid = (Brows + ROWSPC - 1) / ROWSPC;   // 147 for B=65536
    fused_kernel<<<grid, TPB, SMEM_BYTES>>>(x, W, bsp, fcw, fcb, out, Brows);
}